// round 11
// baseline (speedup 1.0000x reference)
#include <cuda_runtime.h>
#include <cuda_bf16.h>
#include <cstdint>

#define NB   4
#define NPIX 4096
#define CH   256
#define Dh   32
#define M_TOTAL (NB * NPIX)   // 16384

// scratch: split q/k/v rows = [hi(32) | lo(32)] bf16 = 128 B
__device__ __align__(16) __nv_bfloat16 g_q2[M_TOTAL * 64];
__device__ __align__(16) __nv_bfloat16 g_k2[M_TOTAL * 64];
__device__ __align__(16) __nv_bfloat16 g_v2[M_TOTAL * 64];
// unnormalized attention partials, one set per j-half
__device__ __align__(16) float g_oacc[2][M_TOTAL * Dh];
__device__ float g_lsum[2][M_TOTAL];

// ---------------------------------------------------------------------------
// warp-MMA helpers (arch-generic PTX: valid on plain sm_103 target)
// ---------------------------------------------------------------------------
__device__ __forceinline__ uint32_t smem_u32(const void* p) {
    uint32_t a;
    asm("{ .reg .u64 t; cvta.to.shared.u64 t, %1; cvt.u32.u64 %0, t; }" : "=r"(a) : "l"(p));
    return a;
}
__device__ __forceinline__ void mma16816(float* c, const uint32_t* a, const uint32_t* b) {
    asm volatile(
        "mma.sync.aligned.m16n8k16.row.col.f32.bf16.bf16.f32 "
        "{%0,%1,%2,%3}, {%4,%5,%6,%7}, {%8,%9}, {%0,%1,%2,%3};"
        : "+f"(c[0]), "+f"(c[1]), "+f"(c[2]), "+f"(c[3])
        : "r"(a[0]), "r"(a[1]), "r"(a[2]), "r"(a[3]), "r"(b[0]), "r"(b[1]));
}
__device__ __forceinline__ void ldsm_x4(uint32_t* r, uint32_t addr) {
    asm volatile("ldmatrix.sync.aligned.m8n8.x4.shared.b16 {%0,%1,%2,%3}, [%4];"
                 : "=r"(r[0]), "=r"(r[1]), "=r"(r[2]), "=r"(r[3]) : "r"(addr));
}
__device__ __forceinline__ void ldsm_x4_t(uint32_t* r, uint32_t addr) {
    asm volatile("ldmatrix.sync.aligned.m8n8.x4.trans.shared.b16 {%0,%1,%2,%3}, [%4];"
                 : "=r"(r[0]), "=r"(r[1]), "=r"(r[2]), "=r"(r[3]) : "r"(addr));
}
__device__ __forceinline__ float ex2f(float x) {
    float y; asm("ex2.approx.ftz.f32 %0, %1;" : "=f"(y) : "f"(x)); return y;
}
__device__ __forceinline__ uint32_t packbf(float hi, float lo) {
    uint32_t r;
    asm("cvt.rn.bf16x2.f32 %0, %1, %2;" : "=r"(r) : "f"(hi), "f"(lo));
    return r;
}

#define ROW_B 144   // 72 bf16 per padded smem row (conflict-free ldmatrix)

// copy a 128-row x 64-bf16 tile (128B payload) into padded smem
__device__ __forceinline__ void load_tile(const __nv_bfloat16* __restrict__ src,
                                          char* __restrict__ dst, int t) {
    const int row = t >> 1, hf = t & 1;
    const uint4* s = (const uint4*)(src + (size_t)row * 64) + hf * 4;
    char* d = dst + row * ROW_B + hf * 64;
#pragma unroll
    for (int u = 0; u < 4; u++) ((uint4*)d)[u] = s[u];
}

// ===========================================================================
// Kernel 1 (v3): projections -> split bf16, k pre-scaled by log2(e).
// 32-row tiles (grid 512 -> ~3.5 CTA/SM), x transposed in smem.
// Thread = (output col tx, 4-row group g): 1 LDS.128 + 3 LDS.32 + 12 FFMA /kk.
// ===========================================================================
#define XP 36   // padded xsT row: 32 floats + 4 pad (16B-aligned rows)

__global__ __launch_bounds__(256) void proj_kernel(
    const float* __restrict__ x,
    const float* __restrict__ Wf,
    const float* __restrict__ Wg,
    const float* __restrict__ Wh)
{
    __shared__ float xsT[64][XP];   // [k][m]  9 KB
    __shared__ float ws[64][96];    // [k][c*32+tx] 24 KB

    const int t  = threadIdx.x;
    const int m0 = blockIdx.x * 32;
    const int tx = t & 31;          // output column
    const int g  = t >> 5;          // row group: rows g*4 .. g*4+3

    float acc[4][3];
#pragma unroll
    for (int r = 0; r < 4; r++)
#pragma unroll
        for (int c = 0; c < 3; c++) acc[r][c] = 0.f;

    const int lm = t & 31;          // row for x loads
    const int kq = t >> 5;          // k-octet group 0..7

    for (int kc = 0; kc < 4; kc++) {
        const int k0 = kc * 64;
        __syncthreads();
        // load x chunk transposed: thread loads 8 k of row lm, scatters to xsT[k][m]
#pragma unroll
        for (int u = 0; u < 2; u++) {
            const int kk = kq * 8 + u * 4;
            float4 v = *(const float4*)(x + (size_t)(m0 + lm) * CH + k0 + kk);
            xsT[kk + 0][lm] = v.x;
            xsT[kk + 1][lm] = v.y;
            xsT[kk + 2][lm] = v.z;
            xsT[kk + 3][lm] = v.w;
        }
        // load weight chunk: 64 k x 32 cols per matrix
#pragma unroll
        for (int u = 0; u < 2; u++) {
            int idx = t + u * 256;
            int kk = idx >> 3, c4 = idx & 7;
            *(float4*)(&ws[kk][c4 * 4])      = *(const float4*)(Wf + (size_t)(k0 + kk) * Dh + c4 * 4);
            *(float4*)(&ws[kk][32 + c4 * 4]) = *(const float4*)(Wg + (size_t)(k0 + kk) * Dh + c4 * 4);
            *(float4*)(&ws[kk][64 + c4 * 4]) = *(const float4*)(Wh + (size_t)(k0 + kk) * Dh + c4 * 4);
        }
        __syncthreads();

#pragma unroll 8
        for (int kk = 0; kk < 64; kk++) {
            const float4 xa = *(const float4*)(&xsT[kk][g * 4]);   // broadcast
            const float wq = ws[kk][tx];
            const float wk = ws[kk][32 + tx];
            const float wv = ws[kk][64 + tx];
            const float xr[4] = { xa.x, xa.y, xa.z, xa.w };
#pragma unroll
            for (int r = 0; r < 4; r++) {
                acc[r][0] += xr[r] * wq;
                acc[r][1] += xr[r] * wk;
                acc[r][2] += xr[r] * wv;
            }
        }
    }

#pragma unroll
    for (int r = 0; r < 4; r++) {
        int m = m0 + g * 4 + r;
        acc[r][1] *= 1.4426950408889634f;   // fold log2(e) into k
        __nv_bfloat16* dsts[3] = { g_q2, g_k2, g_v2 };
#pragma unroll
        for (int c = 0; c < 3; c++) {
            float a = acc[r][c];
            __nv_bfloat16 hi = __float2bfloat16(a);
            __nv_bfloat16 lo = __float2bfloat16(a - __bfloat162float(hi));
            dsts[c][(size_t)m * 64 + tx]      = hi;
            dsts[c][(size_t)m * 64 + 32 + tx] = lo;
        }
    }
}

// ===========================================================================
// Kernel 2: HMMA flash attention, j-split in 2 halves (softmax sum is
// partitionable: no rescale). CTA = (i-tile, batch, j-half); 16 j-iters.
// Writes UNNORMALIZED (Oacc, lsum) partials; out_kernel combines.
// (R8 configuration — synchronous tile loads; HMMA-pipe-bound.)
// ===========================================================================
#define SMK 0
#define SMQ 18432
#define SMV 36864
#define SM_TOTAL 55296

__global__ __launch_bounds__(256, 2) void attn_kernel()
{
    extern __shared__ __align__(16) char smem[];
    const int t    = threadIdx.x;
    const int lane = t & 31;
    const int w    = t >> 5;
    const int b    = blockIdx.y;
    const int i0   = blockIdx.x * 128;
    const int jz   = blockIdx.z;             // j-half: 0 or 1

    const __nv_bfloat16* kb = g_k2 + (size_t)b * NPIX * 64;
    const __nv_bfloat16* qb = g_q2 + (size_t)b * NPIX * 64;
    const __nv_bfloat16* vb = g_v2 + (size_t)b * NPIX * 64;

    const uint32_t skb = smem_u32(smem + SMK);
    const uint32_t sqb = smem_u32(smem + SMQ);
    const uint32_t svb = smem_u32(smem + SMV);

    // stage K tile, build resident A fragments (4 k16-ranges x 4 regs)
    load_tile(kb + (size_t)i0 * 64, smem + SMK, t);
    __syncthreads();

    const int l7 = lane & 7;
    const uint32_t a_row = l7 + ((lane >> 3) & 1) * 8;
    const uint32_t a_col = ((lane >> 4) & 1) * 16;          // bytes
    const uint32_t q_row = l7 + ((lane >> 4) & 1) * 8;
    const uint32_t q_col = ((lane >> 3) & 1) * 16;          // bytes

    uint32_t KA[4][4];
#pragma unroll
    for (int kr = 0; kr < 4; kr++)
        ldsm_x4(KA[kr], skb + (w * 16 + a_row) * ROW_B + kr * 32 + a_col);

    float Oa[4][4];
#pragma unroll
    for (int d = 0; d < 4; d++)
#pragma unroll
        for (int c = 0; c < 4; c++) Oa[d][c] = 0.f;
    float lsum0 = 0.f, lsum1 = 0.f;

    for (int it = 0; it < 16; it++) {
        const size_t j0 = (size_t)jz * 2048 + (size_t)it * 128;
        __syncthreads();   // previous iter's smem reads (and KA ldsm) done
        load_tile(qb + j0 * 64, smem + SMQ, t);
        load_tile(vb + j0 * 64, smem + SMV, t);
        __syncthreads();

#pragma unroll
        for (int nt2 = 0; nt2 < 8; nt2++) {
            // ---- GEMM1: S(16 x 16j) = Kh·Qh + Kh·Ql + Kl·Qh ----
            uint32_t bq[4][4];
#pragma unroll
            for (int kr = 0; kr < 4; kr++)
                ldsm_x4(bq[kr], sqb + (nt2 * 16 + q_row) * ROW_B + kr * 32 + q_col);

            float s[8];
#pragma unroll
            for (int c = 0; c < 8; c++) s[c] = 0.f;
#pragma unroll
            for (int ntl = 0; ntl < 2; ntl++) {
                float* sc = s + ntl * 4;
                mma16816(sc, KA[0], &bq[0][2 * ntl]);   // Kh . Qh (k 0-15)
                mma16816(sc, KA[1], &bq[1][2 * ntl]);   // Kh . Qh (k 16-31)
                mma16816(sc, KA[0], &bq[2][2 * ntl]);   // Kh . Ql
                mma16816(sc, KA[1], &bq[3][2 * ntl]);
                mma16816(sc, KA[2], &bq[0][2 * ntl]);   // Kl . Qh
                mma16816(sc, KA[3], &bq[1][2 * ntl]);
            }

            // ---- epilogue: p = 2^s ; split to bf16 hi/lo ; row sums ----
            float e0 = ex2f(s[0]), e1 = ex2f(s[1]), e2 = ex2f(s[2]), e3 = ex2f(s[3]);
            float e4 = ex2f(s[4]), e5 = ex2f(s[5]), e6 = ex2f(s[6]), e7 = ex2f(s[7]);
            lsum0 += (e0 + e1) + (e4 + e5);
            lsum1 += (e2 + e3) + (e6 + e7);

            uint32_t ph[4], pl[4];
            ph[0] = packbf(e1, e0); ph[1] = packbf(e3, e2);
            ph[2] = packbf(e5, e4); ph[3] = packbf(e7, e6);
            {
                float h;
                h = __uint_as_float(ph[0] << 16);          float l0 = e0 - h;
                h = __uint_as_float(ph[0] & 0xffff0000u);  float l1 = e1 - h;
                pl[0] = packbf(l1, l0);
                h = __uint_as_float(ph[1] << 16);          l0 = e2 - h;
                h = __uint_as_float(ph[1] & 0xffff0000u);  l1 = e3 - h;
                pl[1] = packbf(l1, l0);
                h = __uint_as_float(ph[2] << 16);          l0 = e4 - h;
                h = __uint_as_float(ph[2] & 0xffff0000u);  l1 = e5 - h;
                pl[2] = packbf(l1, l0);
                h = __uint_as_float(ph[3] << 16);          l0 = e6 - h;
                h = __uint_as_float(ph[3] & 0xffff0000u);  l1 = e7 - h;
                pl[3] = packbf(l1, l0);
            }

            // ---- GEMM2: O += Ph·Vh + Ph·Vl + Pl·Vh  (j block = nt2*16) ----
#pragma unroll
            for (int dp = 0; dp < 2; dp++) {
                uint32_t bh[4], bl[4];
                const uint32_t va = svb + (nt2 * 16 + a_row) * ROW_B + dp * 32 + a_col;
                ldsm_x4_t(bh, va);          // V hi (d cols 0-31)
                ldsm_x4_t(bl, va + 64);     // V lo (d cols 32-63)
                mma16816(Oa[dp * 2],     ph, bh);
                mma16816(Oa[dp * 2 + 1], ph, bh + 2);
                mma16816(Oa[dp * 2],     ph, bl);
                mma16816(Oa[dp * 2 + 1], ph, bl + 2);
                mma16816(Oa[dp * 2],     pl, bh);
                mma16816(Oa[dp * 2 + 1], pl, bh + 2);
            }
        }
    }

    // ---- store unnormalized partials ----
    lsum0 += __shfl_xor_sync(0xffffffffu, lsum0, 1);
    lsum0 += __shfl_xor_sync(0xffffffffu, lsum0, 2);
    lsum1 += __shfl_xor_sync(0xffffffffu, lsum1, 1);
    lsum1 += __shfl_xor_sync(0xffffffffu, lsum1, 2);

    const int r0 = i0 + w * 16 + (lane >> 2);
    float* op0 = g_oacc[jz] + ((size_t)b * NPIX + r0) * Dh;
    float* op1 = op0 + 8 * Dh;
    const int cb = 2 * (lane & 3);
#pragma unroll
    for (int dn = 0; dn < 4; dn++) {
        float2 u0 = { Oa[dn][0], Oa[dn][1] };
        float2 u1 = { Oa[dn][2], Oa[dn][3] };
        *(float2*)(op0 + dn * 8 + cb) = u0;
        *(float2*)(op1 + dn * 8 + cb) = u1;
    }
    if ((lane & 3) == 0) {
        g_lsum[jz][(size_t)b * NPIX + r0]     = lsum0;
        g_lsum[jz][(size_t)b * NPIX + r0 + 8] = lsum1;
    }
}

// ===========================================================================
// Kernel 3: combine j-halves, normalize, out = gamma * (o @ Wv) + x
// ===========================================================================
__global__ __launch_bounds__(256) void out_kernel(
    const float* __restrict__ x,
    const float* __restrict__ Wv,
    const float* __restrict__ gamma_p,
    float* __restrict__ out)
{
    __shared__ float wvs[32][256];
    __shared__ float os[32][32];
    __shared__ float linv[32];

    const int t  = threadIdx.x;
    const int m0 = blockIdx.x * 32;

#pragma unroll
    for (int u = 0; u < 8; u++) {
        int idx = t + u * 256;
        int r = idx >> 6, c4 = idx & 63;
        *(float4*)(&wvs[r][c4 * 4]) = *(const float4*)(Wv + (size_t)r * CH + c4 * 4);
    }
    if (t < 32) {
        float l = g_lsum[0][m0 + t] + g_lsum[1][m0 + t];
        linv[t] = 1.0f / l;
    }
    __syncthreads();
    {
        int r = t >> 3, c4 = t & 7;
        const float4 a = *(const float4*)(g_oacc[0] + (size_t)(m0 + r) * Dh + c4 * 4);
        const float4 bb = *(const float4*)(g_oacc[1] + (size_t)(m0 + r) * Dh + c4 * 4);
        const float li = linv[r];
        float4 o = { (a.x + bb.x) * li, (a.y + bb.y) * li,
                     (a.z + bb.z) * li, (a.w + bb.w) * li };
        *(float4*)(&os[r][c4 * 4]) = o;
    }
    __syncthreads();

    const int lane = t & 31;
    const int w    = t >> 5;

    float acc[4][8];
#pragma unroll
    for (int r = 0; r < 4; r++)
#pragma unroll
        for (int c = 0; c < 8; c++) acc[r][c] = 0.f;

#pragma unroll
    for (int kk = 0; kk < 32; kk++) {
        float wv[8];
#pragma unroll
        for (int c = 0; c < 8; c++) wv[c] = wvs[kk][lane + c * 32];
#pragma unroll
        for (int r = 0; r < 4; r++) {
            float xo = os[w * 4 + r][kk];
#pragma unroll
            for (int c = 0; c < 8; c++) acc[r][c] += xo * wv[c];
        }
    }

    const float g = *gamma_p;
#pragma unroll
    for (int r = 0; r < 4; r++) {
        int m = m0 + w * 4 + r;
#pragma unroll
        for (int c = 0; c < 8; c++) {
            int col = lane + c * 32;
            out[(size_t)m * CH + col] = g * acc[r][c] + x[(size_t)m * CH + col];
        }
    }
}

// ===========================================================================
extern "C" void kernel_launch(void* const* d_in, const int* in_sizes, int n_in,
                              void* d_out, int out_size)
{
    const float* x     = (const float*)d_in[0];
    const float* Wf    = (const float*)d_in[1];
    const float* Wg    = (const float*)d_in[2];
    const float* Wh    = (const float*)d_in[3];
    const float* Wv    = (const float*)d_in[4];
    const float* gamma = (const float*)d_in[5];
    float* out = (float*)d_out;

    cudaFuncSetAttribute(attn_kernel, cudaFuncAttributeMaxDynamicSharedMemorySize, SM_TOTAL);

    proj_kernel<<<M_TOTAL / 32, 256>>>(x, Wf, Wg, Wh);
    attn_kernel<<<dim3(NPIX / 128, NB, 2), 256, SM_TOTAL>>>();
    out_kernel<<<M_TOTAL / 32, 256>>>(x, Wv, gamma, out);
}

// round 12
// speedup vs baseline: 1.1468x; 1.1468x over previous
#include <cuda_runtime.h>
#include <cuda_bf16.h>
#include <cstdint>

#define NB   4
#define NPIX 4096
#define CH   256
#define Dh   32
#define M_TOTAL (NB * NPIX)   // 16384

// scratch: split q/k/v rows = [hi(32) | lo(32)] bf16 = 128 B
__device__ __align__(16) __nv_bfloat16 g_q2[M_TOTAL * 64];
__device__ __align__(16) __nv_bfloat16 g_k2[M_TOTAL * 64];
__device__ __align__(16) __nv_bfloat16 g_v2[M_TOTAL * 64];
// unnormalized attention partials, one set per j-half
__device__ __align__(16) float g_oacc[2][M_TOTAL * Dh];
__device__ float g_lsum[2][M_TOTAL];

// ---------------------------------------------------------------------------
// warp-MMA helpers (arch-generic PTX: valid on plain sm_103 target)
// ---------------------------------------------------------------------------
__device__ __forceinline__ uint32_t smem_u32(const void* p) {
    uint32_t a;
    asm("{ .reg .u64 t; cvta.to.shared.u64 t, %1; cvt.u32.u64 %0, t; }" : "=r"(a) : "l"(p));
    return a;
}
__device__ __forceinline__ void mma16816(float* c, const uint32_t* a, const uint32_t* b) {
    asm volatile(
        "mma.sync.aligned.m16n8k16.row.col.f32.bf16.bf16.f32 "
        "{%0,%1,%2,%3}, {%4,%5,%6,%7}, {%8,%9}, {%0,%1,%2,%3};"
        : "+f"(c[0]), "+f"(c[1]), "+f"(c[2]), "+f"(c[3])
        : "r"(a[0]), "r"(a[1]), "r"(a[2]), "r"(a[3]), "r"(b[0]), "r"(b[1]));
}
__device__ __forceinline__ void ldsm_x4(uint32_t* r, uint32_t addr) {
    asm volatile("ldmatrix.sync.aligned.m8n8.x4.shared.b16 {%0,%1,%2,%3}, [%4];"
                 : "=r"(r[0]), "=r"(r[1]), "=r"(r[2]), "=r"(r[3]) : "r"(addr));
}
__device__ __forceinline__ void ldsm_x4_t(uint32_t* r, uint32_t addr) {
    asm volatile("ldmatrix.sync.aligned.m8n8.x4.trans.shared.b16 {%0,%1,%2,%3}, [%4];"
                 : "=r"(r[0]), "=r"(r[1]), "=r"(r[2]), "=r"(r[3]) : "r"(addr));
}
__device__ __forceinline__ float ex2f(float x) {
    float y; asm("ex2.approx.ftz.f32 %0, %1;" : "=f"(y) : "f"(x)); return y;
}
__device__ __forceinline__ uint32_t packbf(float hi, float lo) {
    uint32_t r;
    asm("cvt.rn.bf16x2.f32 %0, %1, %2;" : "=r"(r) : "f"(hi), "f"(lo));
    return r;
}

#define ROW_B 144   // 72 bf16 per padded smem row (conflict-free ldmatrix)

// copy a 128-row x 64-bf16 tile (128B payload) into padded smem
__device__ __forceinline__ void load_tile(const __nv_bfloat16* __restrict__ src,
                                          char* __restrict__ dst, int t) {
    const int row = t >> 1, hf = t & 1;
    const uint4* s = (const uint4*)(src + (size_t)row * 64) + hf * 4;
    char* d = dst + row * ROW_B + hf * 64;
#pragma unroll
    for (int u = 0; u < 4; u++) ((uint4*)d)[u] = s[u];
}

// ===========================================================================
// Kernel 1 (v4): HMMA projections. q|k|v = x @ {Wf,Wg,Wh} with split-bf16
// 3-term products (xh.Wh + xh.Wl + xl.Wh). k pre-scaled by log2(e) (folded
// into Wg at conversion). CTA = 128 rows, 8 warps x 16 rows; K chunked by 64.
// ===========================================================================
#define XROW  272                   // 64 hi bf16 (128B) | 64 lo (128B) | 16B pad
#define PSMX  0                     // x tile: 128 rows x 272 B = 34816
#define PSMW  34816                 // W^T tile: 96 rows x 272 B = 26112
#define PSM_TOTAL 60928

__global__ __launch_bounds__(256, 1) void proj_kernel(
    const float* __restrict__ x,
    const float* __restrict__ Wf,
    const float* __restrict__ Wg,
    const float* __restrict__ Wh)
{
    extern __shared__ __align__(16) char psm[];
    const int t    = threadIdx.x;
    const int lane = t & 31;
    const int w    = t >> 5;
    const int m0   = blockIdx.x * 128;

    char* xs  = psm + PSMX;
    char* wts = psm + PSMW;
    const uint32_t xbase = smem_u32(xs);
    const uint32_t wbase = smem_u32(wts);

    // fragment lane maps (same as verified attn kernel)
    const int l7 = lane & 7;
    const uint32_t a_row = l7 + ((lane >> 3) & 1) * 8;
    const uint32_t a_col = ((lane >> 4) & 1) * 16;          // bytes
    const uint32_t q_row = l7 + ((lane >> 4) & 1) * 8;
    const uint32_t q_col = ((lane >> 3) & 1) * 16;          // bytes

    float acc[3][4][4];
#pragma unroll
    for (int m = 0; m < 3; m++)
#pragma unroll
        for (int f = 0; f < 4; f++)
#pragma unroll
            for (int c = 0; c < 4; c++) acc[m][f][c] = 0.f;

    for (int kc = 0; kc < 4; kc++) {
        const int k0 = kc * 64;
        __syncthreads();

        // ---- convert x chunk: 128 rows x 64 k -> hi|lo bf16 (coalesced) ----
        {
            const int f  = t & 15;          // float4 index within row (k = f*4)
            const int r0 = t >> 4;          // 16 rows per pass
#pragma unroll
            for (int p = 0; p < 8; p++) {
                const int row = r0 + p * 16;
                float4 v = *(const float4*)(x + (size_t)(m0 + row) * CH + k0 + f * 4);
                char* dr = xs + row * XROW;
                uint32_t h0 = packbf(v.y, v.x);
                uint32_t h1 = packbf(v.w, v.z);
                float b0 = __uint_as_float(h0 << 16);
                float b1 = __uint_as_float(h0 & 0xffff0000u);
                uint32_t l0 = packbf(v.y - b1, v.x - b0);
                b0 = __uint_as_float(h1 << 16);
                b1 = __uint_as_float(h1 & 0xffff0000u);
                uint32_t l1 = packbf(v.w - b1, v.z - b0);
                *(uint32_t*)(dr + f * 8)           = h0;
                *(uint32_t*)(dr + f * 8 + 4)       = h1;
                *(uint32_t*)(dr + 128 + f * 8)     = l0;
                *(uint32_t*)(dr + 128 + f * 8 + 4) = l1;
            }
        }
        // ---- convert W chunk -> W^T [n=96 rows][64 k] hi|lo (coalesced) ----
        {
            const int c4   = t & 7;         // float4 col index
            const int rid0 = t >> 3;        // (mat,kk) row id, 32 per pass
#pragma unroll
            for (int p = 0; p < 6; p++) {
                const int rid = rid0 + p * 32;      // 0..191
                const int mat = rid >> 6;
                const int kk  = rid & 63;
                const float* Wm = (mat == 0) ? Wf : (mat == 1) ? Wg : Wh;
                float4 v = *(const float4*)(Wm + (size_t)(k0 + kk) * Dh + c4 * 4);
                if (mat == 1) {
                    v.x *= 1.4426950408889634f; v.y *= 1.4426950408889634f;
                    v.z *= 1.4426950408889634f; v.w *= 1.4426950408889634f;
                }
                const float vals[4] = { v.x, v.y, v.z, v.w };
#pragma unroll
                for (int j = 0; j < 4; j++) {
                    const int n = mat * 32 + c4 * 4 + j;
                    __nv_bfloat16 hi = __float2bfloat16(vals[j]);
                    __nv_bfloat16 lo = __float2bfloat16(vals[j] - __bfloat162float(hi));
                    char* dr = wts + n * XROW;
                    *(__nv_bfloat16*)(dr + kk * 2)       = hi;
                    *(__nv_bfloat16*)(dr + 128 + kk * 2) = lo;
                }
            }
        }
        __syncthreads();

        // ---- MMAs: terms xh.Wh + xh.Wl + xl.Wh over 4 k16 chunks ----
#pragma unroll
        for (int ah = 0; ah < 2; ah++) {            // x half: 0=hi, 1=lo
            const int nterms = (ah == 0) ? 2 : 1;   // W halves to pair with
#pragma unroll
            for (int k16 = 0; k16 < 4; k16++) {
                uint32_t a[4];
                ldsm_x4(a, xbase + (w * 16 + a_row) * XROW + ah * 128 + k16 * 32 + a_col);
#pragma unroll
                for (int tb = 0; tb < 2; tb++) {
                    if (tb >= nterms) break;
                    const int bh = (ah == 0) ? tb : 0;
#pragma unroll
                    for (int mat = 0; mat < 3; mat++) {
#pragma unroll
                        for (int nt = 0; nt < 2; nt++) {
                            uint32_t bfr[4];
                            ldsm_x4(bfr, wbase + (mat * 32 + nt * 16 + q_row) * XROW
                                          + bh * 128 + k16 * 32 + q_col);
                            mma16816(acc[mat][nt * 2],     a, bfr);
                            mma16816(acc[mat][nt * 2 + 1], a, bfr + 2);
                        }
                    }
                }
            }
        }
    }

    // ---- epilogue: split C frags to hi/lo bf16, store to g_q2/k2/v2 ----
    const int r0g = m0 + w * 16 + (lane >> 2);
    const int cb  = 2 * (lane & 3);
    __nv_bfloat16* dsts[3] = { g_q2, g_k2, g_v2 };
#pragma unroll
    for (int mat = 0; mat < 3; mat++) {
        char* gbase = (char*)dsts[mat];
#pragma unroll
        for (int f = 0; f < 4; f++) {
            const int n = f * 8 + cb;
#pragma unroll
            for (int half = 0; half < 2; half++) {   // C rows r0g (+0) and r0g+8
                const float v0 = acc[mat][f][half * 2];
                const float v1 = acc[mat][f][half * 2 + 1];
                uint32_t h = packbf(v1, v0);
                float b0 = __uint_as_float(h << 16);
                float b1 = __uint_as_float(h & 0xffff0000u);
                uint32_t lw = packbf(v1 - b1, v0 - b0);
                char* base = gbase + (size_t)(r0g + half * 8) * 128 + n * 2;
                *(uint32_t*)base        = h;
                *(uint32_t*)(base + 64) = lw;
            }
        }
    }
}

// ===========================================================================
// Kernel 2: HMMA flash attention, j-split in 2 halves (softmax sum is
// partitionable: no rescale). CTA = (i-tile, batch, j-half); 16 j-iters.
// Writes UNNORMALIZED (Oacc, lsum) partials; out_kernel combines.
// (R8/R10 configuration — unchanged, HMMA-pipe-bound.)
// ===========================================================================
#define SMK 0
#define SMQ 18432
#define SMV 36864
#define SM_TOTAL 55296

__global__ __launch_bounds__(256, 2) void attn_kernel()
{
    extern __shared__ __align__(16) char smem[];
    const int t    = threadIdx.x;
    const int lane = t & 31;
    const int w    = t >> 5;
    const int b    = blockIdx.y;
    const int i0   = blockIdx.x * 128;
    const int jz   = blockIdx.z;             // j-half: 0 or 1

    const __nv_bfloat16* kb = g_k2 + (size_t)b * NPIX * 64;
    const __nv_bfloat16* qb = g_q2 + (size_t)b * NPIX * 64;
    const __nv_bfloat16* vb = g_v2 + (size_t)b * NPIX * 64;

    const uint32_t skb = smem_u32(smem + SMK);
    const uint32_t sqb = smem_u32(smem + SMQ);
    const uint32_t svb = smem_u32(smem + SMV);

    // stage K tile, build resident A fragments (4 k16-ranges x 4 regs)
    load_tile(kb + (size_t)i0 * 64, smem + SMK, t);
    __syncthreads();

    const int l7 = lane & 7;
    const uint32_t a_row = l7 + ((lane >> 3) & 1) * 8;
    const uint32_t a_col = ((lane >> 4) & 1) * 16;          // bytes
    const uint32_t q_row = l7 + ((lane >> 4) & 1) * 8;
    const uint32_t q_col = ((lane >> 3) & 1) * 16;          // bytes

    uint32_t KA[4][4];
#pragma unroll
    for (int kr = 0; kr < 4; kr++)
        ldsm_x4(KA[kr], skb + (w * 16 + a_row) * ROW_B + kr * 32 + a_col);

    float Oa[4][4];
#pragma unroll
    for (int d = 0; d < 4; d++)
#pragma unroll
        for (int c = 0; c < 4; c++) Oa[d][c] = 0.f;
    float lsum0 = 0.f, lsum1 = 0.f;

    for (int it = 0; it < 16; it++) {
        const size_t j0 = (size_t)jz * 2048 + (size_t)it * 128;
        __syncthreads();   // previous iter's smem reads (and KA ldsm) done
        load_tile(qb + j0 * 64, smem + SMQ, t);
        load_tile(vb + j0 * 64, smem + SMV, t);
        __syncthreads();

#pragma unroll
        for (int nt2 = 0; nt2 < 8; nt2++) {
            // ---- GEMM1: S(16 x 16j) = Kh·Qh + Kh·Ql + Kl·Qh ----
            uint32_t bq[4][4];
#pragma unroll
            for (int kr = 0; kr < 4; kr++)
                ldsm_x4(bq[kr], sqb + (nt2 * 16 + q_row) * ROW_B + kr * 32 + q_col);

            float s[8];
#pragma unroll
            for (int c = 0; c < 8; c++) s[c] = 0.f;
#pragma unroll
            for (int ntl = 0; ntl < 2; ntl++) {
                float* sc = s + ntl * 4;
                mma16816(sc, KA[0], &bq[0][2 * ntl]);   // Kh . Qh (k 0-15)
                mma16816(sc, KA[1], &bq[1][2 * ntl]);   // Kh . Qh (k 16-31)
                mma16816(sc, KA[0], &bq[2][2 * ntl]);   // Kh . Ql
                mma16816(sc, KA[1], &bq[3][2 * ntl]);
                mma16816(sc, KA[2], &bq[0][2 * ntl]);   // Kl . Qh
                mma16816(sc, KA[3], &bq[1][2 * ntl]);
            }

            // ---- epilogue: p = 2^s ; split to bf16 hi/lo ; row sums ----
            float e0 = ex2f(s[0]), e1 = ex2f(s[1]), e2 = ex2f(s[2]), e3 = ex2f(s[3]);
            float e4 = ex2f(s[4]), e5 = ex2f(s[5]), e6 = ex2f(s[6]), e7 = ex2f(s[7]);
            lsum0 += (e0 + e1) + (e4 + e5);
            lsum1 += (e2 + e3) + (e6 + e7);

            uint32_t ph[4], pl[4];
            ph[0] = packbf(e1, e0); ph[1] = packbf(e3, e2);
            ph[2] = packbf(e5, e4); ph[3] = packbf(e7, e6);
            {
                float h;
                h = __uint_as_float(ph[0] << 16);          float l0 = e0 - h;
                h = __uint_as_float(ph[0] & 0xffff0000u);  float l1 = e1 - h;
                pl[0] = packbf(l1, l0);
                h = __uint_as_float(ph[1] << 16);          l0 = e2 - h;
                h = __uint_as_float(ph[1] & 0xffff0000u);  l1 = e3 - h;
                pl[1] = packbf(l1, l0);
                h = __uint_as_float(ph[2] << 16);          l0 = e4 - h;
                h = __uint_as_float(ph[2] & 0xffff0000u);  l1 = e5 - h;
                pl[2] = packbf(l1, l0);
                h = __uint_as_float(ph[3] << 16);          l0 = e6 - h;
                h = __uint_as_float(ph[3] & 0xffff0000u);  l1 = e7 - h;
                pl[3] = packbf(l1, l0);
            }

            // ---- GEMM2: O += Ph·Vh + Ph·Vl + Pl·Vh  (j block = nt2*16) ----
#pragma unroll
            for (int dp = 0; dp < 2; dp++) {
                uint32_t bh[4], bl[4];
                const uint32_t va = svb + (nt2 * 16 + a_row) * ROW_B + dp * 32 + a_col;
                ldsm_x4_t(bh, va);          // V hi (d cols 0-31)
                ldsm_x4_t(bl, va + 64);     // V lo (d cols 32-63)
                mma16816(Oa[dp * 2],     ph, bh);
                mma16816(Oa[dp * 2 + 1], ph, bh + 2);
                mma16816(Oa[dp * 2],     ph, bl);
                mma16816(Oa[dp * 2 + 1], ph, bl + 2);
                mma16816(Oa[dp * 2],     pl, bh);
                mma16816(Oa[dp * 2 + 1], pl, bh + 2);
            }
        }
    }

    // ---- store unnormalized partials ----
    lsum0 += __shfl_xor_sync(0xffffffffu, lsum0, 1);
    lsum0 += __shfl_xor_sync(0xffffffffu, lsum0, 2);
    lsum1 += __shfl_xor_sync(0xffffffffu, lsum1, 1);
    lsum1 += __shfl_xor_sync(0xffffffffu, lsum1, 2);

    const int r0 = i0 + w * 16 + (lane >> 2);
    float* op0 = g_oacc[jz] + ((size_t)b * NPIX + r0) * Dh;
    float* op1 = op0 + 8 * Dh;
    const int cb = 2 * (lane & 3);
#pragma unroll
    for (int dn = 0; dn < 4; dn++) {
        float2 u0 = { Oa[dn][0], Oa[dn][1] };
        float2 u1 = { Oa[dn][2], Oa[dn][3] };
        *(float2*)(op0 + dn * 8 + cb) = u0;
        *(float2*)(op1 + dn * 8 + cb) = u1;
    }
    if ((lane & 3) == 0) {
        g_lsum[jz][(size_t)b * NPIX + r0]     = lsum0;
        g_lsum[jz][(size_t)b * NPIX + r0 + 8] = lsum1;
    }
}

// ===========================================================================
// Kernel 3: combine j-halves, normalize, out = gamma * (o @ Wv) + x
// ===========================================================================
__global__ __launch_bounds__(256) void out_kernel(
    const float* __restrict__ x,
    const float* __restrict__ Wv,
    const float* __restrict__ gamma_p,
    float* __restrict__ out)
{
    __shared__ float wvs[32][256];
    __shared__ float os[32][32];
    __shared__ float linv[32];

    const int t  = threadIdx.x;
    const int m0 = blockIdx.x * 32;

#pragma unroll
    for (int u = 0; u < 8; u++) {
        int idx = t + u * 256;
        int r = idx >> 6, c4 = idx & 63;
        *(float4*)(&wvs[r][c4 * 4]) = *(const float4*)(Wv + (size_t)r * CH + c4 * 4);
    }
    if (t < 32) {
        float l = g_lsum[0][m0 + t] + g_lsum[1][m0 + t];
        linv[t] = 1.0f / l;
    }
    __syncthreads();
    {
        int r = t >> 3, c4 = t & 7;
        const float4 a = *(const float4*)(g_oacc[0] + (size_t)(m0 + r) * Dh + c4 * 4);
        const float4 bb = *(const float4*)(g_oacc[1] + (size_t)(m0 + r) * Dh + c4 * 4);
        const float li = linv[r];
        float4 o = { (a.x + bb.x) * li, (a.y + bb.y) * li,
                     (a.z + bb.z) * li, (a.w + bb.w) * li };
        *(float4*)(&os[r][c4 * 4]) = o;
    }
    __syncthreads();

    const int lane = t & 31;
    const int w    = t >> 5;

    float acc[4][8];
#pragma unroll
    for (int r = 0; r < 4; r++)
#pragma unroll
        for (int c = 0; c < 8; c++) acc[r][c] = 0.f;

#pragma unroll
    for (int kk = 0; kk < 32; kk++) {
        float wv[8];
#pragma unroll
        for (int c = 0; c < 8; c++) wv[c] = wvs[kk][lane + c * 32];
#pragma unroll
        for (int r = 0; r < 4; r++) {
            float xo = os[w * 4 + r][kk];
#pragma unroll
            for (int c = 0; c < 8; c++) acc[r][c] += xo * wv[c];
        }
    }

    const float g = *gamma_p;
#pragma unroll
    for (int r = 0; r < 4; r++) {
        int m = m0 + w * 4 + r;
#pragma unroll
        for (int c = 0; c < 8; c++) {
            int col = lane + c * 32;
            out[(size_t)m * CH + col] = g * acc[r][c] + x[(size_t)m * CH + col];
        }
    }
}

// ===========================================================================
extern "C" void kernel_launch(void* const* d_in, const int* in_sizes, int n_in,
                              void* d_out, int out_size)
{
    const float* x     = (const float*)d_in[0];
    const float* Wf    = (const float*)d_in[1];
    const float* Wg    = (const float*)d_in[2];
    const float* Wh    = (const float*)d_in[3];
    const float* Wv    = (const float*)d_in[4];
    const float* gamma = (const float*)d_in[5];
    float* out = (float*)d_out;

    cudaFuncSetAttribute(proj_kernel, cudaFuncAttributeMaxDynamicSharedMemorySize, PSM_TOTAL);
    cudaFuncSetAttribute(attn_kernel, cudaFuncAttributeMaxDynamicSharedMemorySize, SM_TOTAL);

    proj_kernel<<<M_TOTAL / 128, 256, PSM_TOTAL>>>(x, Wf, Wg, Wh);
    attn_kernel<<<dim3(NPIX / 128, NB, 2), 256, SM_TOTAL>>>();
    out_kernel<<<M_TOTAL / 32, 256>>>(x, Wv, gamma, out);
}